// round 1
// baseline (speedup 1.0000x reference)
#include <cuda_runtime.h>
#include <math.h>

// Problem constants
#define BB 2
#define TT 2048
#define CC 1024
#define HH 16
#define DD 64
#define MTOT (BB * TT)   // 4096

// GEMM tiling
#define BM 128
#define BN 128
#define BKT 16
#define TM 8
#define TN 8

// Scratch (device globals: no allocation allowed)
__device__ float g_q[BB * HH * TT * DD];
__device__ float g_k[BB * HH * TT * DD];
__device__ float g_v[BB * HH * TT * DD];
__device__ float g_att[BB * TT * CC];

struct Ptr3 {
    const float* w[3];
    const float* bias[3];
    float* out[3];
};

// C[m,n] = sum_k A[m,k] * W[n,k] + bias[n]
// HEAD_SPLIT: write out as [B,H,T,D] instead of [M,N]
template <bool HEAD_SPLIT>
__global__ __launch_bounds__(256) void sgemm_kernel(const float* __restrict__ A, Ptr3 p)
{
    const int z = blockIdx.z;
    const float* __restrict__ Wt   = p.w[z];
    const float* __restrict__ bias = p.bias[z];
    float* __restrict__ out        = p.out[z];

    __shared__ float As[BKT][BM];
    __shared__ float Bs[BKT][BN];

    const int m0  = blockIdx.y * BM;
    const int n0  = blockIdx.x * BN;
    const int tid = threadIdx.x;
    const int tx  = tid % 16;  // n direction
    const int ty  = tid / 16;  // m direction

    float acc[TM][TN];
#pragma unroll
    for (int i = 0; i < TM; i++)
#pragma unroll
        for (int j = 0; j < TN; j++) acc[i][j] = 0.f;

    for (int k0 = 0; k0 < CC; k0 += BKT) {
        // Load A tile: 128 rows x 16 k -> As[k][m] (transposed for coalesced compute reads)
#pragma unroll
        for (int it = 0; it < 2; ++it) {
            int idx = tid + it * 256;            // 0..511 float4 slots
            int row = idx >> 2;                  // 0..127
            int kq  = (idx & 3) << 2;            // 0,4,8,12
            float4 v = *reinterpret_cast<const float4*>(
                &A[(size_t)(m0 + row) * CC + k0 + kq]);
            As[kq + 0][row] = v.x;
            As[kq + 1][row] = v.y;
            As[kq + 2][row] = v.z;
            As[kq + 3][row] = v.w;
        }
#pragma unroll
        for (int it = 0; it < 2; ++it) {
            int idx = tid + it * 256;
            int row = idx >> 2;
            int kq  = (idx & 3) << 2;
            float4 v = *reinterpret_cast<const float4*>(
                &Wt[(size_t)(n0 + row) * CC + k0 + kq]);
            Bs[kq + 0][row] = v.x;
            Bs[kq + 1][row] = v.y;
            Bs[kq + 2][row] = v.z;
            Bs[kq + 3][row] = v.w;
        }
        __syncthreads();

#pragma unroll
        for (int kk = 0; kk < BKT; ++kk) {
            float af[TM], bf[TN];
            const float4* arow = reinterpret_cast<const float4*>(&As[kk][0]);
            const float4* brow = reinterpret_cast<const float4*>(&Bs[kk][0]);
            float4 a0 = arow[ty * 2], a1 = arow[ty * 2 + 1];
            float4 b0 = brow[tx * 2], b1 = brow[tx * 2 + 1];
            af[0] = a0.x; af[1] = a0.y; af[2] = a0.z; af[3] = a0.w;
            af[4] = a1.x; af[5] = a1.y; af[6] = a1.z; af[7] = a1.w;
            bf[0] = b0.x; bf[1] = b0.y; bf[2] = b0.z; bf[3] = b0.w;
            bf[4] = b1.x; bf[5] = b1.y; bf[6] = b1.z; bf[7] = b1.w;
#pragma unroll
            for (int i = 0; i < TM; i++)
#pragma unroll
                for (int j = 0; j < TN; j++) acc[i][j] += af[i] * bf[j];
        }
        __syncthreads();
    }

#pragma unroll
    for (int i = 0; i < TM; i++) {
        int m = m0 + ty * TM + i;
#pragma unroll
        for (int j = 0; j < TN; j++) {
            int n    = n0 + tx * TN + j;
            float v  = acc[i][j] + bias[n];
            if (HEAD_SPLIT) {
                int b = m >> 11;        // / TT
                int t = m & (TT - 1);
                int h = n >> 6;         // / DD
                int d = n & (DD - 1);
                out[(((size_t)(b * HH + h)) * TT + t) * DD + d] = v;
            } else {
                out[(size_t)m * CC + n] = v;
            }
        }
    }
}

// Flash attention, causal. One thread = one query row (Q row + O accumulator
// in registers). K/V tiles (64 rows x 64 d) in smem, read as broadcast float4.
__global__ __launch_bounds__(128, 2) void flash_attn_kernel(
    const float* __restrict__ Qg, const float* __restrict__ Kg,
    const float* __restrict__ Vg, float* __restrict__ Og)
{
    constexpr int BQ  = 128;
    constexpr int BKV = 64;

    const int bh = blockIdx.y;                         // 0..B*H-1
    const int qb = (gridDim.x - 1) - blockIdx.x;       // reversed: big work first
    const int qrow = qb * BQ + threadIdx.x;
    const size_t base = (size_t)bh * TT * DD;

    __shared__ float Ks[BKV * DD];
    __shared__ float Vs[BKV * DD];

    float q[DD];
    {
        const float4* qp = reinterpret_cast<const float4*>(Qg + base + (size_t)qrow * DD);
#pragma unroll
        for (int i = 0; i < DD / 4; i++) {
            float4 t4 = qp[i];
            q[4 * i + 0] = t4.x; q[4 * i + 1] = t4.y;
            q[4 * i + 2] = t4.z; q[4 * i + 3] = t4.w;
        }
    }

    float o[DD];
#pragma unroll
    for (int d = 0; d < DD; d++) o[d] = 0.f;
    float mrow = -INFINITY, lrow = 0.f;
    const float scale = 0.125f;  // 1/sqrt(64)

    const int nkb = (qb * BQ + BQ - 1) / BKV + 1;
    for (int kb = 0; kb < nkb; ++kb) {
        __syncthreads();
        {
            const float4* ksrc = reinterpret_cast<const float4*>(Kg + base + (size_t)kb * BKV * DD);
            const float4* vsrc = reinterpret_cast<const float4*>(Vg + base + (size_t)kb * BKV * DD);
            float4* kdst = reinterpret_cast<float4*>(Ks);
            float4* vdst = reinterpret_cast<float4*>(Vs);
#pragma unroll
            for (int i = 0; i < 8; i++) kdst[threadIdx.x + i * 128] = ksrc[threadIdx.x + i * 128];
#pragma unroll
            for (int i = 0; i < 8; i++) vdst[threadIdx.x + i * 128] = vsrc[threadIdx.x + i * 128];
        }
        __syncthreads();

        if (kb * BKV <= qrow) {
            const float4* K4 = reinterpret_cast<const float4*>(Ks);
            const float4* V4 = reinterpret_cast<const float4*>(Vs);
#pragma unroll 1
            for (int ch = 0; ch < BKV / 16; ++ch) {
                const int jbase = kb * BKV + ch * 16;
                if (jbase > qrow) break;

                float s[16];
#pragma unroll
                for (int jj = 0; jj < 16; jj++) {
                    const int j = ch * 16 + jj;
                    float s0 = 0.f, s1 = 0.f, s2 = 0.f, s3 = 0.f;
#pragma unroll
                    for (int dd = 0; dd < 16; ++dd) {
                        float4 kv = K4[j * 16 + dd];
                        s0 += q[4 * dd + 0] * kv.x;
                        s1 += q[4 * dd + 1] * kv.y;
                        s2 += q[4 * dd + 2] * kv.z;
                        s3 += q[4 * dd + 3] * kv.w;
                    }
                    float sv = ((s0 + s1) + (s2 + s3)) * scale;
                    if (jbase + jj > qrow) sv = -INFINITY;
                    s[jj] = sv;
                }

                float mb = s[0];
#pragma unroll
                for (int jj = 1; jj < 16; jj++) mb = fmaxf(mb, s[jj]);
                const float mnew = fmaxf(mrow, mb);
                const float corr = __expf(mrow - mnew);
                lrow *= corr;
#pragma unroll
                for (int d = 0; d < DD; d++) o[d] *= corr;

#pragma unroll
                for (int jj = 0; jj < 16; jj++) {
                    const float p = __expf(s[jj] - mnew);
                    lrow += p;
                    const int j = ch * 16 + jj;
#pragma unroll
                    for (int dd = 0; dd < 16; ++dd) {
                        float4 vv = V4[j * 16 + dd];
                        o[4 * dd + 0] += p * vv.x;
                        o[4 * dd + 1] += p * vv.y;
                        o[4 * dd + 2] += p * vv.z;
                        o[4 * dd + 3] += p * vv.w;
                    }
                }
                mrow = mnew;
            }
        }
    }

    // Write attention output directly in [B,T,C] layout (head re-merge fused)
    const float inv = 1.f / lrow;
    const int b = bh / HH, h = bh % HH;
    float* dst = Og + ((size_t)(b * TT + qrow)) * CC + h * DD;
#pragma unroll
    for (int i = 0; i < DD / 4; i++) {
        float4 t4 = make_float4(o[4 * i + 0] * inv, o[4 * i + 1] * inv,
                                o[4 * i + 2] * inv, o[4 * i + 3] * inv);
        reinterpret_cast<float4*>(dst)[i] = t4;
    }
}

extern "C" void kernel_launch(void* const* d_in, const int* in_sizes, int n_in,
                              void* d_out, int out_size)
{
    const float* x  = (const float*)d_in[0];
    // d_in[1] = att_mask (int32 causal tril) — causality is applied analytically
    const float* wq = (const float*)d_in[2];
    const float* bq = (const float*)d_in[3];
    const float* wk = (const float*)d_in[4];
    const float* bk = (const float*)d_in[5];
    const float* wv = (const float*)d_in[6];
    const float* bv = (const float*)d_in[7];
    const float* wp = (const float*)d_in[8];
    const float* bp = (const float*)d_in[9];
    float* out = (float*)d_out;

    float *qg, *kg, *vg, *attg;
    cudaGetSymbolAddress((void**)&qg, g_q);
    cudaGetSymbolAddress((void**)&kg, g_k);
    cudaGetSymbolAddress((void**)&vg, g_v);
    cudaGetSymbolAddress((void**)&attg, g_att);

    // 1) Fused QKV projections -> [B,H,T,D]
    {
        Ptr3 p;
        p.w[0] = wq;  p.bias[0] = bq;  p.out[0] = qg;
        p.w[1] = wk;  p.bias[1] = bk;  p.out[1] = kg;
        p.w[2] = wv;  p.bias[2] = bv;  p.out[2] = vg;
        dim3 grid(CC / BN, MTOT / BM, 3);
        sgemm_kernel<true><<<grid, 256>>>(x, p);
    }

    // 2) Causal flash attention -> [B,T,C] (head merge fused into the store)
    {
        dim3 grid(TT / 128, BB * HH);
        flash_attn_kernel<<<grid, 128>>>(qg, kg, vg, attg);
    }

    // 3) Output projection -> d_out [B,T,C]
    {
        Ptr3 p;
        p.w[0] = wp;  p.bias[0] = bp;  p.out[0] = out;
        p.w[1] = wp;  p.bias[1] = bp;  p.out[1] = out;
        p.w[2] = wp;  p.bias[2] = bp;  p.out[2] = out;
        dim3 grid(CC / BN, MTOT / BM, 1);
        sgemm_kernel<false><<<grid, 256>>>(attg, p);
    }
}

// round 3
// speedup vs baseline: 3.9927x; 3.9927x over previous
#include <cuda_runtime.h>
#include <cuda_bf16.h>
#include <math.h>
#include <stdint.h>

// Problem constants
#define BB 2
#define TT 2048
#define CC 1024
#define HH 16
#define DD 64
#define MTOT 4096
#define KTOT 3072              // bf16-split-3 K dimension
#define WSZ (CC * KTOT)

// ---------------------------------------------------------------------------
// Device scratch
// ---------------------------------------------------------------------------
__device__ __align__(128) __nv_bfloat16 g_xs[(size_t)MTOT * KTOT];      // x split [hi|lo|hi]
__device__ __align__(128) __nv_bfloat16 g_wcat[(size_t)4 * WSZ];        // wq,wk,wv,wp split [hi|hi|lo]
__device__ __align__(128) __nv_bfloat16 g_atts[(size_t)MTOT * KTOT];    // attention out split [hi|lo|hi]
__device__ __align__(128) __nv_bfloat16 g_qs[(size_t)BB * HH * TT * 192]; // Q' = [Qh|Ql|Qh] * 0.125
__device__ __align__(128) __nv_bfloat16 g_ks[(size_t)BB * HH * TT * 192]; // K' = [Kh|Kh|Kl]
__device__ __align__(128) __nv_bfloat16 g_vs[(size_t)BB * HH * TT * 128]; // V' = [Vh|Vl]

// ---------------------------------------------------------------------------
// PTX helpers (sm_80-class ISA only: compiles under compute_103)
// ---------------------------------------------------------------------------
__device__ __forceinline__ uint32_t smem_u32(const void* p) {
    return (uint32_t)__cvta_generic_to_shared(p);
}

__device__ __forceinline__ void cp16(uint32_t dst, const void* src) {
    asm volatile("cp.async.cg.shared.global [%0], [%1], 16;" :: "r"(dst), "l"(src));
}
#define CP_COMMIT() asm volatile("cp.async.commit_group;" ::: "memory")
#define CP_WAIT0()  asm volatile("cp.async.wait_group 0;" ::: "memory")

__device__ __forceinline__ void ldm_x4(uint32_t* r, uint32_t addr) {
    asm volatile("ldmatrix.sync.aligned.m8n8.x4.shared.b16 {%0,%1,%2,%3}, [%4];"
                 : "=r"(r[0]), "=r"(r[1]), "=r"(r[2]), "=r"(r[3]) : "r"(addr));
}
__device__ __forceinline__ void ldm_x4_t(uint32_t* r, uint32_t addr) {
    asm volatile("ldmatrix.sync.aligned.m8n8.x4.trans.shared.b16 {%0,%1,%2,%3}, [%4];"
                 : "=r"(r[0]), "=r"(r[1]), "=r"(r[2]), "=r"(r[3]) : "r"(addr));
}

__device__ __forceinline__ void mma16816(float* c, const uint32_t* a, const uint32_t* b) {
    asm volatile(
        "mma.sync.aligned.m16n8k16.row.col.f32.bf16.bf16.f32 "
        "{%0,%1,%2,%3}, {%4,%5,%6,%7}, {%8,%9}, {%0,%1,%2,%3};"
        : "+f"(c[0]), "+f"(c[1]), "+f"(c[2]), "+f"(c[3])
        : "r"(a[0]), "r"(a[1]), "r"(a[2]), "r"(a[3]), "r"(b[0]), "r"(b[1]));
}

__device__ __forceinline__ uint32_t pack2(__nv_bfloat16 a, __nv_bfloat16 b) {
    union { __nv_bfloat162 v; uint32_t u; } t;
    t.v = __halves2bfloat162(a, b);
    return t.u;
}
__device__ __forceinline__ void split2(float v, __nv_bfloat16& h, __nv_bfloat16& l) {
    h = __float2bfloat16(v);
    l = __float2bfloat16(v - __bfloat162float(h));
}

// ---------------------------------------------------------------------------
// bf16-split conversion. PAT 0 (activations): [hi, lo, hi]; PAT 1 (weights):
// [hi, hi, lo]. Chunk products: hi*hi + lo*hi + hi*lo == fp32 to ~2^-17.
// ---------------------------------------------------------------------------
template <int PAT>
__global__ __launch_bounds__(256) void split_kernel(const float* __restrict__ in,
                                                    __nv_bfloat16* __restrict__ out)
{
    const size_t r = blockIdx.x;
    const int k = threadIdx.x * 4;
    float4 v = *reinterpret_cast<const float4*>(in + r * CC + k);
    float f[4] = {v.x, v.y, v.z, v.w};
    __nv_bfloat16 hi[4], lo[4];
#pragma unroll
    for (int i = 0; i < 4; i++) split2(f[i], hi[i], lo[i]);
    uint2 hp = make_uint2(pack2(hi[0], hi[1]), pack2(hi[2], hi[3]));
    uint2 lp = make_uint2(pack2(lo[0], lo[1]), pack2(lo[2], lo[3]));
    __nv_bfloat16* o = out + r * KTOT + k;
    *reinterpret_cast<uint2*>(o)          = hp;
    *reinterpret_cast<uint2*>(o + CC)     = (PAT == 0) ? lp : hp;
    *reinterpret_cast<uint2*>(o + 2 * CC) = (PAT == 0) ? hp : lp;
}

// ---------------------------------------------------------------------------
// HMMA GEMM: out[m,n] = sum_k A[m,k]*W[n,k] + bias[n],  A:[M,3072], W:[N,3072]
// CTA 128x128, 8 warps (2x4), warp tile 64x32, K chunk 64, cp.async 2-stage.
// KIND 0: fp32 out [M,C].  KIND 1 (QKV): z=0 -> Q' split, z=1 -> K' split,
// z=2 -> V' split (bf16 globals).
// ---------------------------------------------------------------------------
struct GemmP {
    const __nv_bfloat16* A;
    const __nv_bfloat16* W[3];
    const float* bias[3];
    float* fout;
};

template <int KIND>
__global__ __launch_bounds__(256, 2) void hmma_gemm(GemmP p)
{
    const int z = blockIdx.z;
    const __nv_bfloat16* __restrict__ A = p.A;
    const __nv_bfloat16* __restrict__ W = p.W[z];
    const float* __restrict__ bias = p.bias[z];

    extern __shared__ __align__(1024) char smem[];
    const uint32_t sbase = smem_u32(smem);

    const int m0 = blockIdx.y * 128, n0 = blockIdx.x * 128;
    const int tid = threadIdx.x, lane = tid & 31, wid = tid >> 5;
    const int wm = wid >> 2, wn = wid & 3;

    const __nv_bfloat16* Arow = A + (size_t)m0 * KTOT;
    const __nv_bfloat16* Wrow = W + (size_t)n0 * KTOT;

    auto prefetch = [&](int c, int buf) {
        const uint32_t dstA = sbase + buf * 32768;
        const uint32_t dstW = dstA + 16384;
#pragma unroll
        for (int it = 0; it < 4; ++it) {
            const int idx = tid + it * 256;         // 0..1023
            const int r = idx >> 3, ch = idx & 7;
            const uint32_t sw = (uint32_t)(ch ^ (r & 7)) << 4;
            cp16(dstA + r * 128 + sw, Arow + (size_t)r * KTOT + c * 64 + ch * 8);
            cp16(dstW + r * 128 + sw, Wrow + (size_t)r * KTOT + c * 64 + ch * 8);
        }
        CP_COMMIT();
    };

    float acc[4][4][4];
#pragma unroll
    for (int i = 0; i < 4; i++)
#pragma unroll
        for (int j = 0; j < 4; j++)
#pragma unroll
            for (int q = 0; q < 4; q++) acc[i][j][q] = 0.f;

    prefetch(0, 0);
    for (int kc = 0; kc < 48; ++kc) {
        CP_WAIT0();
        __syncthreads();
        if (kc + 1 < 48) prefetch(kc + 1, (kc + 1) & 1);
        const uint32_t bufA = sbase + (kc & 1) * 32768;
        const uint32_t bufW = bufA + 16384;
#pragma unroll
        for (int k16 = 0; k16 < 4; ++k16) {
            uint32_t a[4][4];
#pragma unroll
            for (int mt = 0; mt < 4; ++mt) {
                const int r = wm * 64 + mt * 16 + (lane & 15);
                const int ch = k16 * 2 + (lane >> 4);
                ldm_x4(a[mt], bufA + r * 128 + ((uint32_t)(ch ^ (r & 7)) << 4));
            }
            uint32_t b[4][2];
#pragma unroll
            for (int pr = 0; pr < 2; ++pr) {
                const int r = wn * 32 + pr * 16 + (lane & 7) + ((lane >> 4) << 3);
                const int ch = k16 * 2 + ((lane >> 3) & 1);
                uint32_t t4[4];
                ldm_x4(t4, bufW + r * 128 + ((uint32_t)(ch ^ (r & 7)) << 4));
                b[pr * 2][0] = t4[0]; b[pr * 2][1] = t4[1];
                b[pr * 2 + 1][0] = t4[2]; b[pr * 2 + 1][1] = t4[3];
            }
#pragma unroll
            for (int mt = 0; mt < 4; ++mt)
#pragma unroll
                for (int nt = 0; nt < 4; ++nt)
                    mma16816(acc[mt][nt], a[mt], b[nt]);
        }
        __syncthreads();
    }

    // Epilogue
    const int r0g = m0 + wm * 64 + (lane >> 2);
    const int nbase = n0 + wn * 32 + 2 * (lane & 3);
#pragma unroll
    for (int mt = 0; mt < 4; ++mt) {
        const int m = r0g + mt * 16;
#pragma unroll
        for (int nt = 0; nt < 4; ++nt) {
            const int n = nbase + nt * 8;
            float v0 = acc[mt][nt][0] + bias[n];
            float v1 = acc[mt][nt][1] + bias[n + 1];
            float v2 = acc[mt][nt][2] + bias[n];
            float v3 = acc[mt][nt][3] + bias[n + 1];
            if (KIND == 0) {
                *reinterpret_cast<float2*>(p.fout + (size_t)m * CC + n) = make_float2(v0, v1);
                *reinterpret_cast<float2*>(p.fout + (size_t)(m + 8) * CC + n) = make_float2(v2, v3);
            } else {
                if (z == 0) { v0 *= 0.125f; v1 *= 0.125f; v2 *= 0.125f; v3 *= 0.125f; }
                const int hh = n >> 6, d = n & 63;
#pragma unroll
                for (int rr = 0; rr < 2; ++rr) {
                    const int mm = m + rr * 8;
                    const float a0 = rr ? v2 : v0, a1 = rr ? v3 : v1;
                    const int b = mm >> 11, t = mm & (TT - 1);
                    const size_t row = ((size_t)(b * HH + hh)) * TT + t;
                    __nv_bfloat16 h0, l0, h1, l1;
                    split2(a0, h0, l0);
                    split2(a1, h1, l1);
                    const uint32_t hp = pack2(h0, h1), lp = pack2(l0, l1);
                    if (z == 0) {
                        __nv_bfloat16* q = g_qs + row * 192 + d;
                        *(uint32_t*)q = hp; *(uint32_t*)(q + 64) = lp; *(uint32_t*)(q + 128) = hp;
                    } else if (z == 1) {
                        __nv_bfloat16* q = g_ks + row * 192 + d;
                        *(uint32_t*)q = hp; *(uint32_t*)(q + 64) = hp; *(uint32_t*)(q + 128) = lp;
                    } else {
                        __nv_bfloat16* q = g_vs + row * 128 + d;
                        *(uint32_t*)q = hp; *(uint32_t*)(q + 64) = lp;
                    }
                }
            }
        }
    }
}

// ---------------------------------------------------------------------------
// Flash attention on HMMA (FA2 sm80 style). CTA: 128 q rows, 8 warps x 16
// rows. KV block 64. Q' frags in regs; K'/V' smem (cp.async double buffer).
// S = Q'K'^T (split-3, scale pre-folded). P split-2 in-register -> PV with
// Vh/Vl (3 mma terms). Output written directly in split-3 proj-A layout.
// ---------------------------------------------------------------------------
__global__ __launch_bounds__(256, 1) void attn_kernel()
{
    extern __shared__ __align__(1024) char smem[];
    const uint32_t sbase = smem_u32(smem);

    const int bh = blockIdx.y;
    const int qb = (int)gridDim.x - 1 - (int)blockIdx.x;  // reversed for balance
    const int q0 = qb * 128;
    const int tid = threadIdx.x, lane = tid & 31, wid = tid >> 5;
    const int qw = q0 + wid * 16;

    // Q' fragments: 12 k16-chunks x 4 regs
    uint32_t aq[12][4];
    {
        const uint32_t* q32 = reinterpret_cast<const uint32_t*>(g_qs) + (size_t)bh * TT * 96;
        const uint32_t* r0p = q32 + (size_t)(qw + (lane >> 2)) * 96;
        const uint32_t* r1p = r0p + 8 * 96;
        const int c0 = lane & 3;
#pragma unroll
        for (int k = 0; k < 12; ++k) {
            aq[k][0] = r0p[k * 8 + c0];
            aq[k][1] = r1p[k * 8 + c0];
            aq[k][2] = r0p[k * 8 + 4 + c0];
            aq[k][3] = r1p[k * 8 + 4 + c0];
        }
    }

    float o[8][4];
#pragma unroll
    for (int i = 0; i < 8; i++)
#pragma unroll
        for (int j = 0; j < 4; j++) o[i][j] = 0.f;
    float m0r = -INFINITY, m1r = -INFINITY, l0 = 0.f, l1 = 0.f;

    const char* ksrc_base = reinterpret_cast<const char*>(g_ks) + (size_t)bh * TT * 384;
    const char* vsrc_base = reinterpret_cast<const char*>(g_vs) + (size_t)bh * TT * 256;

    auto prefetchKV = [&](int kb, int buf) {
        const uint32_t dst = sbase + buf * 40960;
        const char* ks = ksrc_base + (size_t)kb * 64 * 384;
        const char* vs = vsrc_base + (size_t)kb * 64 * 256;
#pragma unroll
        for (int it = 0; it < 10; ++it) {
            const int idx = tid + it * 256;             // 0..2559
            if (idx < 1536) {                            // K': 3 subtiles
                const int sub = idx >> 9, rem = idx & 511, r = rem >> 3, ch = rem & 7;
                cp16(dst + sub * 8192 + r * 128 + ((uint32_t)(ch ^ (r & 7)) << 4),
                     ks + (size_t)r * 384 + sub * 128 + ch * 16);
            } else {                                     // V': 2 subtiles
                const int i2 = idx - 1536;
                const int sub = i2 >> 9, rem = i2 & 511, r = rem >> 3, ch = rem & 7;
                cp16(dst + 24576 + sub * 8192 + r * 128 + ((uint32_t)(ch ^ (r & 7)) << 4),
                     vs + (size_t)r * 256 + sub * 128 + ch * 16);
            }
        }
        CP_COMMIT();
    };

    const int nblk = 2 * qb + 2;
    prefetchKV(0, 0);

    for (int kb = 0; kb < nblk; ++kb) {
        CP_WAIT0();
        __syncthreads();
        if (kb + 1 < nblk) prefetchKV(kb + 1, (kb + 1) & 1);
        const int kv0 = kb * 64;

        if (kv0 <= qw + 15) {
            const uint32_t Kb = sbase + (kb & 1) * 40960;
            const uint32_t Vb = Kb + 24576;

            // ---- S = Q' K'^T ----
            float s[8][4];
#pragma unroll
            for (int i = 0; i < 8; i++)
#pragma unroll
                for (int j = 0; j < 4; j++) s[i][j] = 0.f;
#pragma unroll
            for (int k16 = 0; k16 < 12; ++k16) {
                const int sub = k16 >> 2, kk = k16 & 3;
#pragma unroll
                for (int pr = 0; pr < 4; ++pr) {
                    const int r = pr * 16 + (lane & 7) + ((lane >> 4) << 3);
                    const int ch = kk * 2 + ((lane >> 3) & 1);
                    uint32_t t4[4];
                    ldm_x4(t4, Kb + sub * 8192 + r * 128 + ((uint32_t)(ch ^ (r & 7)) << 4));
                    mma16816(s[pr * 2], aq[k16], t4);
                    mma16816(s[pr * 2 + 1], aq[k16], t4 + 2);
                }
            }

            const int r0 = qw + (lane >> 2), r1 = r0 + 8;
            if (kv0 + 63 > qw) {  // causal mask region
#pragma unroll
                for (int nt = 0; nt < 8; ++nt) {
                    const int j = kv0 + nt * 8 + 2 * (lane & 3);
                    if (j > r0)     s[nt][0] = -INFINITY;
                    if (j + 1 > r0) s[nt][1] = -INFINITY;
                    if (j > r1)     s[nt][2] = -INFINITY;
                    if (j + 1 > r1) s[nt][3] = -INFINITY;
                }
            }

            // ---- online softmax ----
            float b0 = -INFINITY, b1 = -INFINITY;
#pragma unroll
            for (int nt = 0; nt < 8; ++nt) {
                b0 = fmaxf(b0, fmaxf(s[nt][0], s[nt][1]));
                b1 = fmaxf(b1, fmaxf(s[nt][2], s[nt][3]));
            }
            b0 = fmaxf(b0, __shfl_xor_sync(0xffffffffu, b0, 1));
            b0 = fmaxf(b0, __shfl_xor_sync(0xffffffffu, b0, 2));
            b1 = fmaxf(b1, __shfl_xor_sync(0xffffffffu, b1, 1));
            b1 = fmaxf(b1, __shfl_xor_sync(0xffffffffu, b1, 2));
            const float mn0 = fmaxf(m0r, b0), mn1 = fmaxf(m1r, b1);
            const float cor0 = __expf(m0r - mn0), cor1 = __expf(m1r - mn1);
            m0r = mn0; m1r = mn1;
            l0 *= cor0; l1 *= cor1;
#pragma unroll
            for (int nt = 0; nt < 8; ++nt) {
                o[nt][0] *= cor0; o[nt][1] *= cor0;
                o[nt][2] *= cor1; o[nt][3] *= cor1;
            }

            // ---- P = exp(S - m), split-2, repack C-frag -> A-frag ----
            uint32_t ph[4][4], pl[4][4];
#pragma unroll
            for (int kc = 0; kc < 4; ++kc) {
#pragma unroll
                for (int half = 0; half < 2; ++half) {
                    const int nt = kc * 2 + half;
                    const float p0 = __expf(s[nt][0] - mn0);
                    const float p1 = __expf(s[nt][1] - mn0);
                    const float p2 = __expf(s[nt][2] - mn1);
                    const float p3 = __expf(s[nt][3] - mn1);
                    l0 += p0 + p1; l1 += p2 + p3;
                    __nv_bfloat16 h0, lo0, h1, lo1, h2, lo2, h3, lo3;
                    split2(p0, h0, lo0); split2(p1, h1, lo1);
                    split2(p2, h2, lo2); split2(p3, h3, lo3);
                    ph[kc][half * 2]     = pack2(h0, h1);
                    ph[kc][half * 2 + 1] = pack2(h2, h3);
                    pl[kc][half * 2]     = pack2(lo0, lo1);
                    pl[kc][half * 2 + 1] = pack2(lo2, lo3);
                }
            }

            // ---- O += Ph*Vh + Pl*Vh + Ph*Vl ----
#pragma unroll
            for (int kc = 0; kc < 4; ++kc) {
                const int r = kc * 16 + (lane & 7) + ((lane >> 3) & 1) * 8;
#pragma unroll
                for (int dp = 0; dp < 4; ++dp) {
                    const int ch = dp * 2 + (lane >> 4);
                    const uint32_t sw = (uint32_t)(ch ^ (r & 7)) << 4;
                    uint32_t vh[4], vl[4];
                    ldm_x4_t(vh, Vb + r * 128 + sw);
                    ldm_x4_t(vl, Vb + 8192 + r * 128 + sw);
                    mma16816(o[dp * 2],     ph[kc], vh);
                    mma16816(o[dp * 2 + 1], ph[kc], vh + 2);
                    mma16816(o[dp * 2],     pl[kc], vh);
                    mma16816(o[dp * 2 + 1], pl[kc], vh + 2);
                    mma16816(o[dp * 2],     ph[kc], vl);
                    mma16816(o[dp * 2 + 1], ph[kc], vl + 2);
                }
            }
        }
        __syncthreads();
    }

    // ---- epilogue: O/l, write split-3 proj-A layout ----
    l0 += __shfl_xor_sync(0xffffffffu, l0, 1);
    l0 += __shfl_xor_sync(0xffffffffu, l0, 2);
    l1 += __shfl_xor_sync(0xffffffffu, l1, 1);
    l1 += __shfl_xor_sync(0xffffffffu, l1, 2);
    const float inv0 = 1.f / l0, inv1 = 1.f / l1;

    const int b = bh >> 4, hh = bh & 15;
    const int trow = qw + (lane >> 2);
    const size_t mrow = (size_t)(b * TT + trow);
#pragma unroll
    for (int nt = 0; nt < 8; ++nt) {
        const int d = nt * 8 + 2 * (lane & 3);
        const float v0 = o[nt][0] * inv0, v1 = o[nt][1] * inv0;
        const float v2 = o[nt][2] * inv1, v3 = o[nt][3] * inv1;
        __nv_bfloat16 h0, lo0, h1, lo1;
        split2(v0, h0, lo0); split2(v1, h1, lo1);
        uint32_t hp = pack2(h0, h1), lp = pack2(lo0, lo1);
        __nv_bfloat16* p0 = g_atts + mrow * KTOT + hh * 64 + d;
        *(uint32_t*)p0 = hp; *(uint32_t*)(p0 + 1024) = lp; *(uint32_t*)(p0 + 2048) = hp;
        split2(v2, h0, lo0); split2(v3, h1, lo1);
        hp = pack2(h0, h1); lp = pack2(lo0, lo1);
        __nv_bfloat16* p1 = g_atts + (mrow + 8) * KTOT + hh * 64 + d;
        *(uint32_t*)p1 = hp; *(uint32_t*)(p1 + 1024) = lp; *(uint32_t*)(p1 + 2048) = hp;
    }
}

// ---------------------------------------------------------------------------
extern "C" void kernel_launch(void* const* d_in, const int* in_sizes, int n_in,
                              void* d_out, int out_size)
{
    const float* x  = (const float*)d_in[0];
    // d_in[1] = att_mask (causal tril) — applied analytically
    const float* wq = (const float*)d_in[2];
    const float* bq = (const float*)d_in[3];
    const float* wk = (const float*)d_in[4];
    const float* bk = (const float*)d_in[5];
    const float* wv = (const float*)d_in[6];
    const float* bv = (const float*)d_in[7];
    const float* wp = (const float*)d_in[8];
    const float* bp = (const float*)d_in[9];
    float* out = (float*)d_out;

    __nv_bfloat16 *xs, *wcat, *atts;
    cudaGetSymbolAddress((void**)&xs,   g_xs);
    cudaGetSymbolAddress((void**)&wcat, g_wcat);
    cudaGetSymbolAddress((void**)&atts, g_atts);

    cudaFuncSetAttribute(hmma_gemm<0>, cudaFuncAttributeMaxDynamicSharedMemorySize, 65536);
    cudaFuncSetAttribute(hmma_gemm<1>, cudaFuncAttributeMaxDynamicSharedMemorySize, 65536);
    cudaFuncSetAttribute(attn_kernel,  cudaFuncAttributeMaxDynamicSharedMemorySize, 81920);

    // 1) bf16 splits
    split_kernel<0><<<MTOT, 256>>>(x, xs);
    split_kernel<1><<<CC, 256>>>(wq, wcat + 0 * (size_t)WSZ);
    split_kernel<1><<<CC, 256>>>(wk, wcat + 1 * (size_t)WSZ);
    split_kernel<1><<<CC, 256>>>(wv, wcat + 2 * (size_t)WSZ);
    split_kernel<1><<<CC, 256>>>(wp, wcat + 3 * (size_t)WSZ);

    // 2) QKV projections (HMMA) -> Q'/K'/V' split layouts
    {
        GemmP p;
        p.A = xs;
        p.W[0] = wcat + 0 * (size_t)WSZ; p.bias[0] = bq;
        p.W[1] = wcat + 1 * (size_t)WSZ; p.bias[1] = bk;
        p.W[2] = wcat + 2 * (size_t)WSZ; p.bias[2] = bv;
        p.fout = nullptr;
        dim3 grid(CC / 128, MTOT / 128, 3);
        hmma_gemm<1><<<grid, 256, 65536>>>(p);
    }

    // 3) Causal flash attention (HMMA) -> g_atts split-3
    {
        dim3 grid(TT / 128, BB * HH);
        attn_kernel<<<grid, 256, 81920>>>();
    }

    // 4) Output projection (HMMA) -> d_out
    {
        GemmP p;
        p.A = atts;
        p.W[0] = wcat + 3 * (size_t)WSZ; p.bias[0] = bp;
        p.W[1] = p.W[0]; p.bias[1] = bp;
        p.W[2] = p.W[0]; p.bias[2] = bp;
        p.fout = out;
        dim3 grid(CC / 128, MTOT / 128, 1);
        hmma_gemm<0><<<grid, 256, 65536>>>(p);
    }
}